// round 10
// baseline (speedup 1.0000x reference)
#include <cuda_runtime.h>
#include <stdint.h>

#define N_NODES 10000
#define N_EDGES 320000
#define HID 128
#define H3 384
#define NRBF 20
#define EPB 32      // edges per block (edge kernel)
#define KCH 16      // Wf2 k-rows per staged chunk
#define NCHUNK (HID / KCH)   // 8
#define EK_THREADS 256

typedef unsigned long long ull;

// scratch
__device__ float g_x[N_NODES * H3];     // node MLP output [N, 384]
__device__ float g_wf2t[HID * H3];      // Wf2 pre-converted to tf32 bit patterns
__device__ int g_idx64;
__device__ int g_hist[N_NODES];
__device__ int g_cursor[N_NODES];
__device__ int g_perm[N_EDGES];         // edge ids sorted by target

__device__ __forceinline__ float silu_f(float v) {
    return v / (1.0f + __expf(-v));
}
__device__ __forceinline__ ull pack2(float lo, float hi) {
    ull r;
    asm("mov.b64 %0,{%1,%2};" : "=l"(r) : "f"(lo), "f"(hi));
    return r;
}
__device__ __forceinline__ void unpack2(ull v, float& lo, float& hi) {
    asm("mov.b64 {%0,%1},%2;" : "=f"(lo), "=f"(hi) : "l"(v));
}
__device__ __forceinline__ ull fma2(ull a, ull b, ull c) {
    ull d;
    asm("fma.rn.f32x2 %0,%1,%2,%3;" : "=l"(d) : "l"(a), "l"(b), "l"(c));
    return d;
}
__device__ __forceinline__ uint32_t f2tf32(float f) {
    uint32_t r;
    asm("cvt.rna.tf32.f32 %0,%1;" : "=r"(r) : "f"(f));
    return r;
}
__device__ __forceinline__ void mma_tf32(float* d, const uint32_t* a, const uint32_t* b) {
    asm("mma.sync.aligned.m16n8k8.row.col.f32.tf32.tf32.f32 "
        "{%0,%1,%2,%3},{%4,%5,%6,%7},{%8,%9},{%0,%1,%2,%3};"
        : "+f"(d[0]), "+f"(d[1]), "+f"(d[2]), "+f"(d[3])
        : "r"(a[0]), "r"(a[1]), "r"(a[2]), "r"(a[3]), "r"(b[0]), "r"(b[1]));
}
__device__ __forceinline__ void red_add_v2(float* p, float a, float b) {
    asm volatile("red.global.add.v2.f32 [%0],{%1,%2};"
                 :: "l"(p), "f"(a), "f"(b) : "memory");
}
__device__ __forceinline__ void cp_async16(void* sdst, const void* gsrc) {
    unsigned s = (unsigned)__cvta_generic_to_shared(sdst);
    asm volatile("cp.async.cg.shared.global [%0],[%1],16;" :: "r"(s), "l"(gsrc));
}
__device__ __forceinline__ void cp_commit() {
    asm volatile("cp.async.commit_group;");
}
template <int N>
__device__ __forceinline__ void cp_wait() {
    asm volatile("cp.async.wait_group %0;" :: "n"(N));
}

// sorted position s for physical MMA row R (bijection on [0,32))
// R = 16*mt + 8*half + g  <->  s = 4*g + 2*mt + half
__device__ __forceinline__ int sorted_of_row(int R) {
    return 4 * (R & 7) + ((R >> 4) << 1) + ((R >> 3) & 1);
}

// ---------------------------------------------------------------------------
// Kernel 1: out = concat(q, mu); detect idx dtype; zero histogram.
// ---------------------------------------------------------------------------
__global__ void init_out(const float* __restrict__ q,
                         const float* __restrict__ mu,
                         float* __restrict__ out,
                         const int* __restrict__ ei32) {
    if (blockIdx.x == 0 && threadIdx.x == 0) {
        int flag = 1;
        #pragma unroll
        for (int i = 0; i < 16; i++)
            if (ei32[2 * i + 1] != 0) flag = 0;
        g_idx64 = flag;
    }
    int i = blockIdx.x * blockDim.x + threadIdx.x;
    if (i < N_NODES) g_hist[i] = 0;
    const int nq4 = N_NODES * HID / 4;
    const int nm4 = N_NODES * H3 / 4;
    float4* o4 = (float4*)out;
    if (i < nq4)            o4[i] = ((const float4*)q)[i];
    else if (i < nq4 + nm4) o4[i] = ((const float4*)mu)[i - nq4];
}

__global__ void prep_wf2(const float* __restrict__ Wf2) {
    int i = blockIdx.x * blockDim.x + threadIdx.x;
    if (i < HID * H3) g_wf2t[i] = __uint_as_float(f2tf32(Wf2[i]));
}

// --------------------------- counting sort by target -----------------------
__global__ void hist_kernel(const int* __restrict__ ei32,
                            const long long* __restrict__ ei64) {
    int e = blockIdx.x * blockDim.x + threadIdx.x;
    if (e < N_EDGES) {
        int t = g_idx64 ? (int)ei64[e] : ei32[e];
        atomicAdd(&g_hist[t], 1);
    }
}

__global__ __launch_bounds__(1024) void scan_kernel() {
    __shared__ int part[1024];
    const int tid = threadIdx.x;
    const int base = tid * 10;
    int local[10];
    int s = 0;
    #pragma unroll
    for (int j = 0; j < 10; j++) {
        int v = (base + j < N_NODES) ? g_hist[base + j] : 0;
        local[j] = s;
        s += v;
    }
    part[tid] = s;
    __syncthreads();
    const int own = s;
    for (int d = 1; d < 1024; d <<= 1) {
        int v = (tid >= d) ? part[tid - d] : 0;
        __syncthreads();
        part[tid] += v;
        __syncthreads();
    }
    int excl = part[tid] - own;
    #pragma unroll
    for (int j = 0; j < 10; j++)
        if (base + j < N_NODES) g_cursor[base + j] = excl + local[j];
}

__global__ void scatter_kernel(const int* __restrict__ ei32,
                               const long long* __restrict__ ei64) {
    int e = blockIdx.x * blockDim.x + threadIdx.x;
    if (e < N_EDGES) {
        int t = g_idx64 ? (int)ei64[e] : ei32[e];
        int pos = atomicAdd(&g_cursor[t], 1);
        g_perm[pos] = e;
    }
}

// ---------------------------------------------------------------------------
// Kernel 2: node MLP (unchanged). 16 nodes/block.
// ---------------------------------------------------------------------------
__global__ __launch_bounds__(384) void node_mlp(const float* __restrict__ q,
                                                const float* __restrict__ W1,
                                                const float* __restrict__ b1,
                                                const float* __restrict__ W2,
                                                const float* __restrict__ b2) {
    __shared__ float qs[16 * HID];
    __shared__ ull qs2[HID * 8];
    __shared__ ull t1p[H3 * 8];
    const int n0 = blockIdx.x * 16;
    const int tid = threadIdx.x;

    for (int i = tid; i < 16 * HID; i += 384) qs[i] = q[n0 * HID + i];
    __syncthreads();
    for (int i = tid; i < HID * 8; i += 384) {
        int k = i >> 3, j = i & 7;
        qs2[k * 8 + j] = pack2(qs[(2 * j) * HID + k], qs[(2 * j + 1) * HID + k]);
    }
    __syncthreads();

    const int c = tid;
    {
        ull a[8];
        float bb = __ldg(&b1[c]);
        ull bp = pack2(bb, bb);
        #pragma unroll
        for (int j = 0; j < 8; j++) a[j] = bp;
        #pragma unroll 4
        for (int k = 0; k < HID; k++) {
            float w = __ldg(&W1[k * H3 + c]);
            ull ww = pack2(w, w);
            const ulonglong2* qp = (const ulonglong2*)(qs2 + k * 8);
            ulonglong2 p0 = qp[0], p1 = qp[1], p2 = qp[2], p3 = qp[3];
            a[0] = fma2(p0.x, ww, a[0]); a[1] = fma2(p0.y, ww, a[1]);
            a[2] = fma2(p1.x, ww, a[2]); a[3] = fma2(p1.y, ww, a[3]);
            a[4] = fma2(p2.x, ww, a[4]); a[5] = fma2(p2.y, ww, a[5]);
            a[6] = fma2(p3.x, ww, a[6]); a[7] = fma2(p3.y, ww, a[7]);
        }
        #pragma unroll
        for (int j = 0; j < 8; j++) {
            float lo, hi;
            unpack2(a[j], lo, hi);
            t1p[c * 8 + j] = pack2(silu_f(lo), silu_f(hi));
        }
    }
    __syncthreads();
    {
        ull a[8];
        float bb = __ldg(&b2[c]);
        ull bp = pack2(bb, bb);
        #pragma unroll
        for (int j = 0; j < 8; j++) a[j] = bp;
        #pragma unroll 4
        for (int k = 0; k < H3; k++) {
            float w = __ldg(&W2[k * H3 + c]);
            ull ww = pack2(w, w);
            const ulonglong2* tp = (const ulonglong2*)(t1p + k * 8);
            ulonglong2 p0 = tp[0], p1 = tp[1], p2 = tp[2], p3 = tp[3];
            a[0] = fma2(p0.x, ww, a[0]); a[1] = fma2(p0.y, ww, a[1]);
            a[2] = fma2(p1.x, ww, a[2]); a[3] = fma2(p1.y, ww, a[3]);
            a[4] = fma2(p2.x, ww, a[4]); a[5] = fma2(p2.y, ww, a[5]);
            a[6] = fma2(p3.x, ww, a[6]); a[7] = fma2(p3.y, ww, a[7]);
        }
        #pragma unroll
        for (int j = 0; j < 8; j++) {
            float lo, hi;
            unpack2(a[j], lo, hi);
            g_x[(n0 + 2 * j) * H3 + c] = lo;
            g_x[(n0 + 2 * j + 1) * H3 + c] = hi;
        }
    }
}

// ---------------------------------------------------------------------------
// Kernel 3: fused edge kernel — TF32 MMA, sized for 2 CTAs/SM.
// 32 target-sorted edges/block, 256 threads, 8 warps.
// Warp w: cols [w*48, w*48+48) = 6 n8-tiles x 2 m16-tiles (32 edges), K=128.
// ---------------------------------------------------------------------------
// dynamic smem layout:
//   h1s   [32][132] float (tf32 bits) @ 0       (16896 B)
//   wbuf  [2][16][384] float          @ 16896   (49152 B)
//   Wf1s  [NRBF*HID]                  @ 66048   (10240 B)
//   rbfs  [32*NRBF]  (physical rows)  @ 76288   (2560 B)
//   bf1s  [HID]                       @ 78848   (512 B)
//   bf2s  [H3]                        @ 79360   (1536 B)
//   cuts  [32]  (sorted order)        @ 80896   (128 B)
//   uvs   [32*3] (sorted)             @ 81024   (384 B)
//   srcs  [32] int (sorted)           @ 81408   (128 B)
//   tgts  [32] int (sorted)           @ 81536   (128 B)
//   es    [32] int (sorted edge ids)  @ 81664   (128 B)
#define SMEM_EDGE 81792
#define H1PITCH 132

__global__ __launch_bounds__(EK_THREADS, 2) void edge_kernel(
        const int* __restrict__ ei32, const long long* __restrict__ ei64,
        const float* __restrict__ rbf, const float* __restrict__ uv,
        const float* __restrict__ cut,
        const float* __restrict__ Wf1, const float* __restrict__ bf1,
        const float* __restrict__ bf2,
        const float* __restrict__ mu, float* __restrict__ out) {
    extern __shared__ char smem[];
    uint32_t* h1u  = (uint32_t*)smem;
    float*    wbuf = (float*)(smem + 16896);
    float*    Wf1s = (float*)(smem + 66048);
    float*    rbfs = (float*)(smem + 76288);
    float*    bf1s = (float*)(smem + 78848);
    float*    bf2s = (float*)(smem + 79360);
    float*    cuts = (float*)(smem + 80896);
    float*    uvs  = (float*)(smem + 81024);
    int*      srcs = (int*)(smem + 81408);
    int*      tgts = (int*)(smem + 81536);
    int*      es   = (int*)(smem + 81664);

    const int tid = threadIdx.x;
    const int e0 = blockIdx.x * EPB;
    const int F4 = KCH * H3 / 4;  // 1536 float4 per chunk

    // swizzled cp.async staging of a Wf2 chunk (tf32-preconverted source)
    auto stage_chunk = [&](int chunk, int buf) {
        float* dst = wbuf + buf * KCH * H3;
        const float4* src = (const float4*)g_wf2t + chunk * F4;
        for (int i = tid; i < F4; i += EK_THREADS) {
            int kk = i / 96;          // 96 float4 per 384-float row
            int n  = (i % 96) * 4;
            int ns = n ^ ((kk & 3) << 3);
            cp_async16(dst + kk * H3 + ns, src + i);
        }
        cp_commit();
    };

    stage_chunk(0, 0);
    stage_chunk(1, 1);

    if (tid < EPB) es[tid] = g_perm[e0 + tid];
    for (int i = tid; i < NRBF * HID; i += EK_THREADS) Wf1s[i] = Wf1[i];
    for (int i = tid; i < H3; i += EK_THREADS)         bf2s[i] = bf2[i];
    if (tid < HID) bf1s[tid] = bf1[tid];
    __syncthreads();  // es visible

    // per-edge gathers; rbf by PHYSICAL mma row, rest by sorted order
    {
        float4* r4 = (float4*)rbfs;
        const float4* rsrc = (const float4*)rbf;
        for (int i = tid; i < EPB * 5; i += EK_THREADS) {
            int R = i / 5;
            int e = es[sorted_of_row(R)];
            r4[i] = __ldg(rsrc + e * 5 + (i % 5));
        }
        for (int i = tid; i < EPB * 3; i += EK_THREADS) {
            int e = es[i / 3];
            uvs[i] = uv[e * 3 + (i % 3)];
        }
        if (tid < EPB) {
            int e = es[tid];
            cuts[tid] = cut[e];
            if (g_idx64) { tgts[tid] = (int)ei64[e]; srcs[tid] = (int)ei64[N_EDGES + e]; }
            else         { tgts[tid] = ei32[e];      srcs[tid] = ei32[N_EDGES + e]; }
        }
    }
    __syncthreads();

    // Phase A: h1 = tf32(silu(rbf@Wf1+bf1)), physical rows, pitch 132
    for (int i = tid; i < EPB * HID; i += EK_THREADS) {
        int R = i >> 7, j = i & 127;
        float a = bf1s[j];
        #pragma unroll
        for (int k = 0; k < NRBF; k++) a += rbfs[R * NRBF + k] * Wf1s[k * HID + j];
        h1u[R * H1PITCH + j] = f2tf32(silu_f(a));
    }

    // Phase B: TF32 MMA. warp w owns cols [w*48, w*48+48) = 6 n8-tiles.
    const int warp = tid >> 5, lane = tid & 31;
    const int g = lane >> 2, c = lane & 3;
    const int C0 = warp * 48;

    float d[2][6][4];
    #pragma unroll
    for (int mt = 0; mt < 2; mt++)
        #pragma unroll
        for (int j = 0; j < 6; j++)
            #pragma unroll
            for (int r = 0; r < 4; r++) d[mt][j][r] = 0.f;

    #pragma unroll
    for (int chunk = 0; chunk < NCHUNK; chunk++) {
        if (chunk == NCHUNK - 1) cp_wait<0>(); else cp_wait<1>();
        __syncthreads();   // chunk ready (and h1 ready for chunk 0)
        const float* wch = wbuf + (chunk & 1) * KCH * H3;
        #pragma unroll
        for (int ks = 0; ks < 2; ks++) {
            const int kglob = chunk * KCH + 8 * ks;
            uint32_t a[2][4];
            #pragma unroll
            for (int mt = 0; mt < 2; mt++) {
                const uint32_t* hp = h1u + (16 * mt + g) * H1PITCH + kglob + c;
                a[mt][0] = hp[0];
                a[mt][1] = hp[8 * H1PITCH];
                a[mt][2] = hp[4];
                a[mt][3] = hp[8 * H1PITCH + 4];
            }
            uint32_t b[6][2];
            #pragma unroll
            for (int j = 0; j < 6; j++) {
                const int n = C0 + 8 * j + g;
                const int kk0 = 8 * ks + c;
                b[j][0] = ((const uint32_t*)wch)[kk0 * H3 + (n ^ ((kk0 & 3) << 3))];
                const int kk1 = kk0 + 4;
                b[j][1] = ((const uint32_t*)wch)[kk1 * H3 + (n ^ ((kk1 & 3) << 3))];
            }
            #pragma unroll
            for (int mt = 0; mt < 2; mt++)
                #pragma unroll
                for (int j = 0; j < 6; j++)
                    mma_tf32(d[mt][j], a[mt], b[j]);
        }
        __syncthreads();   // all warps done with buffer (chunk&1)
        if (chunk + 2 < NCHUNK) stage_chunk(chunk + 2, chunk & 1);
    }

    // Phase C: epilogue. Lane owns sorted edges s = 4g+idx, idx 0..3;
    // physical row R = 16*(idx>>1) + 8*(idx&1) + g. Run-combined scatter.
    float* outq  = out;
    float* outmu = out + N_NODES * HID;

    int   part[6], jj[6];
    float bb0[6], bb1[6];
    #pragma unroll
    for (int j = 0; j < 6; j++) {
        int C = C0 + 8 * j + 2 * c;
        part[j] = C >> 7;
        jj[j]   = C & 127;
        bb0[j] = bf2s[C];
        bb1[j] = bf2s[C + 1];
    }

    float acc[6][3][2];
    #pragma unroll
    for (int j = 0; j < 6; j++)
        #pragma unroll
        for (int dd = 0; dd < 3; dd++) { acc[j][dd][0] = 0.f; acc[j][dd][1] = 0.f; }

    #pragma unroll
    for (int idx = 0; idx < 4; idx++) {
        const int s = 4 * g + idx;
        const int mt = idx >> 1, h = idx & 1;
        const float cscale = cuts[s];
        const int src = srcs[s], tgt = tgts[s];
        const float* xb = g_x + src * H3;

        #pragma unroll
        for (int j = 0; j < 6; j++) {
            float f0 = (d[mt][j][2 * h]     + bb0[j]) * cscale;
            float f1 = (d[mt][j][2 * h + 1] + bb1[j]) * cscale;
            if (part[j] == 0) {
                float2 x2 = __ldg((const float2*)(xb + jj[j]));
                acc[j][0][0] += x2.x * f0;
                acc[j][0][1] += x2.y * f1;
            } else if (part[j] == 1) {
                float2 x2 = __ldg((const float2*)(xb + HID + jj[j]));
                float t0 = x2.x * f0, t1 = x2.y * f1;
                #pragma unroll
                for (int dd = 0; dd < 3; dd++) {
                    float u = uvs[s * 3 + dd];
                    acc[j][dd][0] += u * t0;
                    acc[j][dd][1] += u * t1;
                }
            } else {
                float2 x2 = __ldg((const float2*)(xb + 2 * HID + jj[j]));
                float t0 = x2.x * f0, t1 = x2.y * f1;
                #pragma unroll
                for (int dd = 0; dd < 3; dd++) {
                    float2 m2 = __ldg((const float2*)(mu + (src * 3 + dd) * HID + jj[j]));
                    acc[j][dd][0] += m2.x * t0;
                    acc[j][dd][1] += m2.y * t1;
                }
            }
        }

        const bool flush = (idx == 3) || (tgts[s + 1] != tgt);
        if (flush) {
            #pragma unroll
            for (int j = 0; j < 6; j++) {
                if (part[j] == 0) {
                    red_add_v2(outq + tgt * HID + jj[j], acc[j][0][0], acc[j][0][1]);
                    acc[j][0][0] = 0.f; acc[j][0][1] = 0.f;
                } else {
                    #pragma unroll
                    for (int dd = 0; dd < 3; dd++) {
                        red_add_v2(outmu + (tgt * 3 + dd) * HID + jj[j],
                                   acc[j][dd][0], acc[j][dd][1]);
                        acc[j][dd][0] = 0.f; acc[j][dd][1] = 0.f;
                    }
                }
            }
        }
    }
}

extern "C" void kernel_launch(void* const* d_in, const int* in_sizes, int n_in,
                              void* d_out, int out_size) {
    const float* q   = (const float*)d_in[0];
    const float* mu  = (const float*)d_in[1];
    const void*  ei  = d_in[2];
    const float* rbf = (const float*)d_in[3];
    const float* uvp = (const float*)d_in[4];
    const float* cut = (const float*)d_in[5];
    const float* W1  = (const float*)d_in[6];
    const float* b1  = (const float*)d_in[7];
    const float* W2  = (const float*)d_in[8];
    const float* b2  = (const float*)d_in[9];
    const float* Wf1 = (const float*)d_in[10];
    const float* bf1 = (const float*)d_in[11];
    const float* Wf2 = (const float*)d_in[12];
    const float* bf2 = (const float*)d_in[13];
    float* out = (float*)d_out;

    cudaFuncSetAttribute(edge_kernel,
                         cudaFuncAttributeMaxDynamicSharedMemorySize, SMEM_EDGE);

    const int total4 = N_NODES * (HID + H3) / 4;
    init_out<<<(total4 + 255) / 256, 256>>>(q, mu, out, (const int*)ei);
    prep_wf2<<<(HID * H3 + 255) / 256, 256>>>(Wf2);
    hist_kernel<<<(N_EDGES + 255) / 256, 256>>>((const int*)ei, (const long long*)ei);
    scan_kernel<<<1, 1024>>>();
    scatter_kernel<<<(N_EDGES + 255) / 256, 256>>>((const int*)ei, (const long long*)ei);
    node_mlp<<<N_NODES / 16, 384>>>(q, W1, b1, W2, b2);
    edge_kernel<<<N_EDGES / EPB, EK_THREADS, SMEM_EDGE>>>(
        (const int*)ei, (const long long*)ei,
        rbf, uvp, cut, Wf1, bf1, bf2, mu, out);
}

// round 11
// speedup vs baseline: 1.1390x; 1.1390x over previous
#include <cuda_runtime.h>
#include <stdint.h>

#define N_NODES 10000
#define N_EDGES 320000
#define HID 128
#define H3 384
#define NRBF 20
#define EPB 32      // edges per block (edge kernel)
#define NPB 32      // nodes per block (node kernel)
#define KCH 16      // weight k-rows per staged chunk
#define NCHUNK (HID / KCH)   // 8
#define EK_THREADS 256

typedef unsigned long long ull;

// scratch
__device__ float g_x[N_NODES * H3];     // node MLP output [N, 384]
__device__ float g_wf2t[HID * H3];      // Wf2 as tf32 bits
__device__ float g_w1t[HID * H3];       // W1 as tf32 bits
__device__ float g_w2t[H3 * H3];        // W2 as tf32 bits
__device__ int g_idx64;
__device__ int g_hist[N_NODES];
__device__ int g_cursor[N_NODES];
__device__ int g_perm[N_EDGES];         // edge ids sorted by target

__device__ __forceinline__ float silu_f(float v) {
    return v / (1.0f + __expf(-v));
}
__device__ __forceinline__ ull pack2(float lo, float hi) {
    ull r;
    asm("mov.b64 %0,{%1,%2};" : "=l"(r) : "f"(lo), "f"(hi));
    return r;
}
__device__ __forceinline__ uint32_t f2tf32(float f) {
    uint32_t r;
    asm("cvt.rna.tf32.f32 %0,%1;" : "=r"(r) : "f"(f));
    return r;
}
__device__ __forceinline__ void mma_tf32(float* d, const uint32_t* a, const uint32_t* b) {
    asm("mma.sync.aligned.m16n8k8.row.col.f32.tf32.tf32.f32 "
        "{%0,%1,%2,%3},{%4,%5,%6,%7},{%8,%9},{%0,%1,%2,%3};"
        : "+f"(d[0]), "+f"(d[1]), "+f"(d[2]), "+f"(d[3])
        : "r"(a[0]), "r"(a[1]), "r"(a[2]), "r"(a[3]), "r"(b[0]), "r"(b[1]));
}
__device__ __forceinline__ void red_add_v2(float* p, float a, float b) {
    asm volatile("red.global.add.v2.f32 [%0],{%1,%2};"
                 :: "l"(p), "f"(a), "f"(b) : "memory");
}
__device__ __forceinline__ void cp_async16(void* sdst, const void* gsrc) {
    unsigned s = (unsigned)__cvta_generic_to_shared(sdst);
    asm volatile("cp.async.cg.shared.global [%0],[%1],16;" :: "r"(s), "l"(gsrc));
}
__device__ __forceinline__ void cp_commit() {
    asm volatile("cp.async.commit_group;");
}
template <int N>
__device__ __forceinline__ void cp_wait() {
    asm volatile("cp.async.wait_group %0;" :: "n"(N));
}

// sorted position s for physical MMA row R (bijection on [0,32))
// R = 16*mt + 8*half + g  <->  s = 4*g + 2*mt + half
__device__ __forceinline__ int sorted_of_row(int R) {
    return 4 * (R & 7) + ((R >> 4) << 1) + ((R >> 3) & 1);
}

// ---------------------------------------------------------------------------
// Kernel 1: out = concat(q, mu); idx dtype; zero hist; tf32-convert weights.
// ---------------------------------------------------------------------------
__global__ void init_out(const float* __restrict__ q,
                         const float* __restrict__ mu,
                         float* __restrict__ out,
                         const int* __restrict__ ei32,
                         const float* __restrict__ Wf2,
                         const float* __restrict__ W1,
                         const float* __restrict__ W2) {
    if (blockIdx.x == 0 && threadIdx.x == 0) {
        int flag = 1;
        #pragma unroll
        for (int i = 0; i < 16; i++)
            if (ei32[2 * i + 1] != 0) flag = 0;
        g_idx64 = flag;
    }
    int i = blockIdx.x * blockDim.x + threadIdx.x;
    if (i < N_NODES) g_hist[i] = 0;
    if (i < HID * H3) {
        g_wf2t[i] = __uint_as_float(f2tf32(Wf2[i]));
        g_w1t[i]  = __uint_as_float(f2tf32(W1[i]));
    }
    if (i < H3 * H3) g_w2t[i] = __uint_as_float(f2tf32(W2[i]));
    const int nq4 = N_NODES * HID / 4;
    const int nm4 = N_NODES * H3 / 4;
    float4* o4 = (float4*)out;
    if (i < nq4)            o4[i] = ((const float4*)q)[i];
    else if (i < nq4 + nm4) o4[i] = ((const float4*)mu)[i - nq4];
}

// --------------------------- counting sort by target -----------------------
__global__ void hist_kernel(const int* __restrict__ ei32,
                            const long long* __restrict__ ei64) {
    int e = blockIdx.x * blockDim.x + threadIdx.x;
    if (e < N_EDGES) {
        int t = g_idx64 ? (int)ei64[e] : ei32[e];
        atomicAdd(&g_hist[t], 1);
    }
}

__global__ __launch_bounds__(1024) void scan_kernel() {
    __shared__ int part[1024];
    const int tid = threadIdx.x;
    const int base = tid * 10;
    int local[10];
    int s = 0;
    #pragma unroll
    for (int j = 0; j < 10; j++) {
        int v = (base + j < N_NODES) ? g_hist[base + j] : 0;
        local[j] = s;
        s += v;
    }
    part[tid] = s;
    __syncthreads();
    const int own = s;
    for (int d = 1; d < 1024; d <<= 1) {
        int v = (tid >= d) ? part[tid - d] : 0;
        __syncthreads();
        part[tid] += v;
        __syncthreads();
    }
    int excl = part[tid] - own;
    #pragma unroll
    for (int j = 0; j < 10; j++)
        if (base + j < N_NODES) g_cursor[base + j] = excl + local[j];
}

__global__ void scatter_kernel(const int* __restrict__ ei32,
                               const long long* __restrict__ ei64) {
    int e = blockIdx.x * blockDim.x + threadIdx.x;
    if (e < N_EDGES) {
        int t = g_idx64 ? (int)ei64[e] : ei32[e];
        int pos = atomicAdd(&g_cursor[t], 1);
        g_perm[pos] = e;
    }
}

// ---------------------------------------------------------------------------
// Kernel 2: node MLP via TF32 MMA. 32 nodes/block, 256 threads, 8 warps.
// GEMM1: [32,128]@[128,384] (silu) -> t1 smem (tf32)
// GEMM2: [32,384]@[384,384] -> g_x
// Weights streamed in 16-row chunks, double-buffered cp.async (32 slots).
// ---------------------------------------------------------------------------
// smem: qs  [32][132] u32 @ 0       (16896)
//       wbuf[2][16][384]  @ 16896   (49152)
//       t1s [32][388] u32 @ 66048   (49664)
#define SMEM_NODE 115712
#define QPITCH 132
#define TPITCH 388

__global__ __launch_bounds__(256) void node_mma(const float* __restrict__ q,
                                                const float* __restrict__ b1,
                                                const float* __restrict__ b2) {
    extern __shared__ char smem[];
    uint32_t* qs   = (uint32_t*)smem;
    float*    wbuf = (float*)(smem + 16896);
    uint32_t* t1s  = (uint32_t*)(smem + 66048);

    const int tid = threadIdx.x;
    const int n0 = blockIdx.x * NPB;
    const int F4 = KCH * H3 / 4;  // 1536

    auto stage_slot = [&](int slot) {
        float* dst = wbuf + (slot & 1) * KCH * H3;
        const float4* src = (slot < NCHUNK)
            ? (const float4*)g_w1t + slot * F4
            : (const float4*)g_w2t + (slot - NCHUNK) * F4;
        for (int i = tid; i < F4; i += 256) {
            int kk = i / 96;
            int n  = (i % 96) * 4;
            int ns = n ^ ((kk & 3) << 3);
            cp_async16(dst + kk * H3 + ns, src + i);
        }
        cp_commit();
    };

    stage_slot(0);
    stage_slot(1);

    // load q tile -> tf32 smem (pitch 132), zero-pad oob rows
    for (int i = tid; i < NPB * (HID / 4); i += 256) {
        int r = i >> 5;            // 32 float4 per row
        int c4 = (i & 31) * 4;
        float4 v = (n0 + r < N_NODES)
            ? __ldg((const float4*)(q + (n0 + r) * HID + c4))
            : make_float4(0.f, 0.f, 0.f, 0.f);
        uint32_t* dst = qs + r * QPITCH + c4;
        dst[0] = f2tf32(v.x); dst[1] = f2tf32(v.y);
        dst[2] = f2tf32(v.z); dst[3] = f2tf32(v.w);
    }

    const int warp = tid >> 5, lane = tid & 31;
    const int g = lane >> 2, c = lane & 3;
    const int C0 = warp * 48;

    float d[2][6][4];
    #pragma unroll
    for (int mt = 0; mt < 2; mt++)
        #pragma unroll
        for (int j = 0; j < 6; j++)
            #pragma unroll
            for (int r = 0; r < 4; r++) d[mt][j][r] = 0.f;

    // ---- GEMM1: K=128 over slots 0..7 (A = qs) ----
    #pragma unroll
    for (int ch = 0; ch < NCHUNK; ch++) {
        cp_wait<1>();
        __syncthreads();
        const float* wch = wbuf + (ch & 1) * KCH * H3;
        #pragma unroll
        for (int ks = 0; ks < 2; ks++) {
            const int kglob = ch * KCH + 8 * ks;
            uint32_t a[2][4];
            #pragma unroll
            for (int mt = 0; mt < 2; mt++) {
                const uint32_t* ap = qs + (16 * mt + g) * QPITCH + kglob + c;
                a[mt][0] = ap[0];
                a[mt][1] = ap[8 * QPITCH];
                a[mt][2] = ap[4];
                a[mt][3] = ap[8 * QPITCH + 4];
            }
            uint32_t b[6][2];
            #pragma unroll
            for (int j = 0; j < 6; j++) {
                const int n = C0 + 8 * j + g;
                const int kk0 = 8 * ks + c;
                b[j][0] = ((const uint32_t*)wch)[kk0 * H3 + (n ^ ((kk0 & 3) << 3))];
                const int kk1 = kk0 + 4;
                b[j][1] = ((const uint32_t*)wch)[kk1 * H3 + (n ^ ((kk1 & 3) << 3))];
            }
            #pragma unroll
            for (int mt = 0; mt < 2; mt++)
                #pragma unroll
                for (int j = 0; j < 6; j++)
                    mma_tf32(d[mt][j], a[mt], b[j]);
        }
        __syncthreads();
        stage_slot(ch + 2);   // slots 2..9 (8,9 = first two W2 chunks)
    }

    // bias + silu -> t1s (tf32), then reset accumulators
    #pragma unroll
    for (int mt = 0; mt < 2; mt++)
        #pragma unroll
        for (int j = 0; j < 6; j++) {
            const int C = C0 + 8 * j + 2 * c;
            const float bb0 = __ldg(&b1[C]), bb1 = __ldg(&b1[C + 1]);
            const int r0 = 16 * mt + g;
            float v0 = silu_f(d[mt][j][0] + bb0);
            float v1 = silu_f(d[mt][j][1] + bb1);
            *(ull*)(t1s + r0 * TPITCH + C) =
                pack2(__uint_as_float(f2tf32(v0)), __uint_as_float(f2tf32(v1)));
            float v2 = silu_f(d[mt][j][2] + bb0);
            float v3 = silu_f(d[mt][j][3] + bb1);
            *(ull*)(t1s + (r0 + 8) * TPITCH + C) =
                pack2(__uint_as_float(f2tf32(v2)), __uint_as_float(f2tf32(v3)));
        }
    #pragma unroll
    for (int mt = 0; mt < 2; mt++)
        #pragma unroll
        for (int j = 0; j < 6; j++)
            #pragma unroll
            for (int r = 0; r < 4; r++) d[mt][j][r] = 0.f;

    // ---- GEMM2: K=384 over W2 chunks 0..23 (A = t1s) ----
    const int NCH2 = H3 / KCH;   // 24
    for (int ch = 0; ch < NCH2; ch++) {
        if (ch == NCH2 - 1) cp_wait<0>(); else cp_wait<1>();
        __syncthreads();          // also orders t1s writes for ch==0
        const float* wch = wbuf + (ch & 1) * KCH * H3;
        #pragma unroll
        for (int ks = 0; ks < 2; ks++) {
            const int kglob = ch * KCH + 8 * ks;
            uint32_t a[2][4];
            #pragma unroll
            for (int mt = 0; mt < 2; mt++) {
                const uint32_t* ap = t1s + (16 * mt + g) * TPITCH + kglob + c;
                a[mt][0] = ap[0];
                a[mt][1] = ap[8 * TPITCH];
                a[mt][2] = ap[4];
                a[mt][3] = ap[8 * TPITCH + 4];
            }
            uint32_t b[6][2];
            #pragma unroll
            for (int j = 0; j < 6; j++) {
                const int n = C0 + 8 * j + g;
                const int kk0 = 8 * ks + c;
                b[j][0] = ((const uint32_t*)wch)[kk0 * H3 + (n ^ ((kk0 & 3) << 3))];
                const int kk1 = kk0 + 4;
                b[j][1] = ((const uint32_t*)wch)[kk1 * H3 + (n ^ ((kk1 & 3) << 3))];
            }
            #pragma unroll
            for (int mt = 0; mt < 2; mt++)
                #pragma unroll
                for (int j = 0; j < 6; j++)
                    mma_tf32(d[mt][j], a[mt], b[j]);
        }
        __syncthreads();
        if (ch + 2 < NCH2) stage_slot(NCHUNK + ch + 2);
    }

    // bias + store to g_x
    #pragma unroll
    for (int mt = 0; mt < 2; mt++)
        #pragma unroll
        for (int j = 0; j < 6; j++) {
            const int C = C0 + 8 * j + 2 * c;
            const float bb0 = __ldg(&b2[C]), bb1 = __ldg(&b2[C + 1]);
            const int r0 = n0 + 16 * mt + g;
            if (r0 < N_NODES)
                *(float2*)(g_x + r0 * H3 + C) =
                    make_float2(d[mt][j][0] + bb0, d[mt][j][1] + bb1);
            if (r0 + 8 < N_NODES)
                *(float2*)(g_x + (r0 + 8) * H3 + C) =
                    make_float2(d[mt][j][2] + bb0, d[mt][j][3] + bb1);
        }
}

// ---------------------------------------------------------------------------
// Kernel 3: fused edge kernel — TF32 MMA, 32 sorted edges/block, 256 thr.
// Epilogue restructured j-outer to cut register pressure (no spills @2 CTA).
// ---------------------------------------------------------------------------
// smem: h1s [32][132] u32 @ 0     (16896)
//       wbuf[2][16][384]  @ 16896 (49152)
//       Wf1s[NRBF*HID]    @ 66048 (10240)
//       rbfs[32*NRBF]     @ 76288 (2560)
//       bf1s[HID]         @ 78848 (512)
//       bf2s[H3]          @ 79360 (1536)
//       cuts[32]          @ 80896 (128)
//       uvs [32*3]        @ 81024 (384)
//       srcs[32] int      @ 81408 (128)
//       tgts[32] int      @ 81536 (128)
//       es  [32] int      @ 81664 (128)
#define SMEM_EDGE 81792
#define H1PITCH 132

__global__ __launch_bounds__(EK_THREADS, 2) void edge_kernel(
        const int* __restrict__ ei32, const long long* __restrict__ ei64,
        const float* __restrict__ rbf, const float* __restrict__ uv,
        const float* __restrict__ cut,
        const float* __restrict__ Wf1, const float* __restrict__ bf1,
        const float* __restrict__ bf2,
        const float* __restrict__ mu, float* __restrict__ out) {
    extern __shared__ char smem[];
    uint32_t* h1u  = (uint32_t*)smem;
    float*    wbuf = (float*)(smem + 16896);
    float*    Wf1s = (float*)(smem + 66048);
    float*    rbfs = (float*)(smem + 76288);
    float*    bf1s = (float*)(smem + 78848);
    float*    bf2s = (float*)(smem + 79360);
    float*    cuts = (float*)(smem + 80896);
    float*    uvs  = (float*)(smem + 81024);
    int*      srcs = (int*)(smem + 81408);
    int*      tgts = (int*)(smem + 81536);
    int*      es   = (int*)(smem + 81664);

    const int tid = threadIdx.x;
    const int e0 = blockIdx.x * EPB;
    const int F4 = KCH * H3 / 4;  // 1536

    auto stage_chunk = [&](int chunk, int buf) {
        float* dst = wbuf + buf * KCH * H3;
        const float4* src = (const float4*)g_wf2t + chunk * F4;
        for (int i = tid; i < F4; i += EK_THREADS) {
            int kk = i / 96;
            int n  = (i % 96) * 4;
            int ns = n ^ ((kk & 3) << 3);
            cp_async16(dst + kk * H3 + ns, src + i);
        }
        cp_commit();
    };

    stage_chunk(0, 0);
    stage_chunk(1, 1);

    if (tid < EPB) es[tid] = g_perm[e0 + tid];
    for (int i = tid; i < NRBF * HID; i += EK_THREADS) Wf1s[i] = Wf1[i];
    for (int i = tid; i < H3; i += EK_THREADS)         bf2s[i] = bf2[i];
    if (tid < HID) bf1s[tid] = bf1[tid];
    __syncthreads();  // es visible

    {
        float4* r4 = (float4*)rbfs;
        const float4* rsrc = (const float4*)rbf;
        for (int i = tid; i < EPB * 5; i += EK_THREADS) {
            int R = i / 5;
            int e = es[sorted_of_row(R)];
            r4[i] = __ldg(rsrc + e * 5 + (i % 5));
        }
        for (int i = tid; i < EPB * 3; i += EK_THREADS) {
            int e = es[i / 3];
            uvs[i] = uv[e * 3 + (i % 3)];
        }
        if (tid < EPB) {
            int e = es[tid];
            cuts[tid] = cut[e];
            if (g_idx64) { tgts[tid] = (int)ei64[e]; srcs[tid] = (int)ei64[N_EDGES + e]; }
            else         { tgts[tid] = ei32[e];      srcs[tid] = ei32[N_EDGES + e]; }
        }
    }
    __syncthreads();

    // Phase A: h1 = tf32(silu(rbf@Wf1+bf1)), physical rows, pitch 132
    for (int i = tid; i < EPB * HID; i += EK_THREADS) {
        int R = i >> 7, j = i & 127;
        float a = bf1s[j];
        #pragma unroll
        for (int k = 0; k < NRBF; k++) a += rbfs[R * NRBF + k] * Wf1s[k * HID + j];
        h1u[R * H1PITCH + j] = f2tf32(silu_f(a));
    }

    // Phase B: TF32 MMA
    const int warp = tid >> 5, lane = tid & 31;
    const int g = lane >> 2, c = lane & 3;
    const int C0 = warp * 48;

    float d[2][6][4];
    #pragma unroll
    for (int mt = 0; mt < 2; mt++)
        #pragma unroll
        for (int j = 0; j < 6; j++)
            #pragma unroll
            for (int r = 0; r < 4; r++) d[mt][j][r] = 0.f;

    #pragma unroll
    for (int chunk = 0; chunk < NCHUNK; chunk++) {
        if (chunk == NCHUNK - 1) cp_wait<0>(); else cp_wait<1>();
        __syncthreads();
        const float* wch = wbuf + (chunk & 1) * KCH * H3;
        #pragma unroll
        for (int ks = 0; ks < 2; ks++) {
            const int kglob = chunk * KCH + 8 * ks;
            uint32_t a[2][4];
            #pragma unroll
            for (int mt = 0; mt < 2; mt++) {
                const uint32_t* hp = h1u + (16 * mt + g) * H1PITCH + kglob + c;
                a[mt][0] = hp[0];
                a[mt][1] = hp[8 * H1PITCH];
                a[mt][2] = hp[4];
                a[mt][3] = hp[8 * H1PITCH + 4];
            }
            uint32_t b[6][2];
            #pragma unroll
            for (int j = 0; j < 6; j++) {
                const int n = C0 + 8 * j + g;
                const int kk0 = 8 * ks + c;
                b[j][0] = ((const uint32_t*)wch)[kk0 * H3 + (n ^ ((kk0 & 3) << 3))];
                const int kk1 = kk0 + 4;
                b[j][1] = ((const uint32_t*)wch)[kk1 * H3 + (n ^ ((kk1 & 3) << 3))];
            }
            #pragma unroll
            for (int mt = 0; mt < 2; mt++)
                #pragma unroll
                for (int j = 0; j < 6; j++)
                    mma_tf32(d[mt][j], a[mt], b[j]);
        }
        __syncthreads();
        if (chunk + 2 < NCHUNK) stage_chunk(chunk + 2, chunk & 1);
    }

    // Phase C: epilogue, j-outer (low register pressure), run-combined scatter
    float* outq  = out;
    float* outmu = out + N_NODES * HID;

    #pragma unroll
    for (int j = 0; j < 6; j++) {
        const int C = C0 + 8 * j + 2 * c;
        const int part = C >> 7, jj = C & 127;
        const float b0 = bf2s[C], b1v = bf2s[C + 1];
        float a0 = 0.f, a1 = 0.f;
        float v[3][2] = {{0.f,0.f},{0.f,0.f},{0.f,0.f}};

        #pragma unroll
        for (int idx = 0; idx < 4; idx++) {
            const int s = 4 * g + idx;
            const int mt = idx >> 1, h = idx & 1;
            const float cs = cuts[s];
            const int src = srcs[s], tgt = tgts[s];
            const float* xb = g_x + src * H3;
            float f0 = (d[mt][j][2 * h]     + b0)  * cs;
            float f1 = (d[mt][j][2 * h + 1] + b1v) * cs;

            if (part == 0) {
                float2 x2 = __ldg((const float2*)(xb + jj));
                a0 += x2.x * f0;
                a1 += x2.y * f1;
            } else if (part == 1) {
                float2 x2 = __ldg((const float2*)(xb + HID + jj));
                float t0 = x2.x * f0, t1 = x2.y * f1;
                #pragma unroll
                for (int dd = 0; dd < 3; dd++) {
                    float u = uvs[s * 3 + dd];
                    v[dd][0] += u * t0;
                    v[dd][1] += u * t1;
                }
            } else {
                float2 x2 = __ldg((const float2*)(xb + 2 * HID + jj));
                float t0 = x2.x * f0, t1 = x2.y * f1;
                #pragma unroll
                for (int dd = 0; dd < 3; dd++) {
                    float2 m2 = __ldg((const float2*)(mu + (src * 3 + dd) * HID + jj));
                    v[dd][0] += m2.x * t0;
                    v[dd][1] += m2.y * t1;
                }
            }

            const bool flush = (idx == 3) || (tgts[s + 1] != tgt);
            if (flush) {
                if (part == 0) {
                    red_add_v2(outq + tgt * HID + jj, a0, a1);
                    a0 = 0.f; a1 = 0.f;
                } else {
                    #pragma unroll
                    for (int dd = 0; dd < 3; dd++) {
                        red_add_v2(outmu + (tgt * 3 + dd) * HID + jj, v[dd][0], v[dd][1]);
                        v[dd][0] = 0.f; v[dd][1] = 0.f;
                    }
                }
            }
        }
    }
}

extern "C" void kernel_launch(void* const* d_in, const int* in_sizes, int n_in,
                              void* d_out, int out_size) {
    const float* q   = (const float*)d_in[0];
    const float* mu  = (const float*)d_in[1];
    const void*  ei  = d_in[2];
    const float* rbf = (const float*)d_in[3];
    const float* uvp = (const float*)d_in[4];
    const float* cut = (const float*)d_in[5];
    const float* W1  = (const float*)d_in[6];
    const float* b1  = (const float*)d_in[7];
    const float* W2  = (const float*)d_in[8];
    const float* b2  = (const float*)d_in[9];
    const float* Wf1 = (const float*)d_in[10];
    const float* bf1 = (const float*)d_in[11];
    const float* Wf2 = (const float*)d_in[12];
    const float* bf2 = (const float*)d_in[13];
    float* out = (float*)d_out;

    cudaFuncSetAttribute(edge_kernel,
                         cudaFuncAttributeMaxDynamicSharedMemorySize, SMEM_EDGE);
    cudaFuncSetAttribute(node_mma,
                         cudaFuncAttributeMaxDynamicSharedMemorySize, SMEM_NODE);

    const int total4 = N_NODES * (HID + H3) / 4;
    init_out<<<(total4 + 255) / 256, 256>>>(q, mu, out, (const int*)ei, Wf2, W1, W2);
    hist_kernel<<<(N_EDGES + 255) / 256, 256>>>((const int*)ei, (const long long*)ei);
    scan_kernel<<<1, 1024>>>();
    scatter_kernel<<<(N_EDGES + 255) / 256, 256>>>((const int*)ei, (const long long*)ei);
    node_mma<<<(N_NODES + NPB - 1) / NPB, 256, SMEM_NODE>>>(q, b1, b2);
    edge_kernel<<<N_EDGES / EPB, EK_THREADS, SMEM_EDGE>>>(
        (const int*)ei, (const long long*)ei,
        rbf, uvp, cut, Wf1, bf1, bf2, mu, out);
}

// round 12
// speedup vs baseline: 1.2658x; 1.1113x over previous
#include <cuda_runtime.h>
#include <stdint.h>

#define N_NODES 10000
#define N_EDGES 320000
#define HID 128
#define H3 384
#define NRBF 20
#define EPB 64      // edges per block (edge kernel)
#define NPB 32      // nodes per block (node kernel)
#define KCH 16      // weight k-rows per staged chunk
#define NCHUNK (HID / KCH)   // 8
#define EK_THREADS 512

typedef unsigned long long ull;

// scratch
__device__ float g_x[N_NODES * H3];     // node MLP output [N, 384]
__device__ float g_wf2t[HID * H3];      // Wf2 as tf32 bits
__device__ float g_w1t[HID * H3];       // W1 as tf32 bits
__device__ float g_w2t[H3 * H3];        // W2 as tf32 bits
__device__ int g_idx64;
__device__ int g_hist[N_NODES];
__device__ int g_cursor[N_NODES];
__device__ int g_perm[N_EDGES];         // edge ids sorted by target

__device__ __forceinline__ float silu_f(float v) {
    return v / (1.0f + __expf(-v));
}
__device__ __forceinline__ ull pack2(float lo, float hi) {
    ull r;
    asm("mov.b64 %0,{%1,%2};" : "=l"(r) : "f"(lo), "f"(hi));
    return r;
}
__device__ __forceinline__ uint32_t f2tf32(float f) {
    uint32_t r;
    asm("cvt.rna.tf32.f32 %0,%1;" : "=r"(r) : "f"(f));
    return r;
}
__device__ __forceinline__ void mma_tf32(float* d, const uint32_t* a, const uint32_t* b) {
    asm("mma.sync.aligned.m16n8k8.row.col.f32.tf32.tf32.f32 "
        "{%0,%1,%2,%3},{%4,%5,%6,%7},{%8,%9},{%0,%1,%2,%3};"
        : "+f"(d[0]), "+f"(d[1]), "+f"(d[2]), "+f"(d[3])
        : "r"(a[0]), "r"(a[1]), "r"(a[2]), "r"(a[3]), "r"(b[0]), "r"(b[1]));
}
__device__ __forceinline__ void red_add_v2(float* p, float a, float b) {
    asm volatile("red.global.add.v2.f32 [%0],{%1,%2};"
                 :: "l"(p), "f"(a), "f"(b) : "memory");
}
__device__ __forceinline__ void cp_async16(void* sdst, const void* gsrc) {
    unsigned s = (unsigned)__cvta_generic_to_shared(sdst);
    asm volatile("cp.async.cg.shared.global [%0],[%1],16;" :: "r"(s), "l"(gsrc));
}
__device__ __forceinline__ void cp_commit() {
    asm volatile("cp.async.commit_group;");
}
template <int N>
__device__ __forceinline__ void cp_wait() {
    asm volatile("cp.async.wait_group %0;" :: "n"(N));
}

// sorted position s for physical MMA row R (bijection on [0,64))
// R = 16*mt + 8*half + g  <->  s = 8*g + 2*mt + half
__device__ __forceinline__ int sorted_of_row(int R) {
    return 8 * (R & 7) + ((R >> 4) << 1) + ((R >> 3) & 1);
}

// ---------------------------------------------------------------------------
// Kernel 1: out = concat(q, mu); idx dtype; zero hist; tf32-convert weights.
// ---------------------------------------------------------------------------
__global__ void init_out(const float* __restrict__ q,
                         const float* __restrict__ mu,
                         float* __restrict__ out,
                         const int* __restrict__ ei32,
                         const float* __restrict__ Wf2,
                         const float* __restrict__ W1,
                         const float* __restrict__ W2) {
    if (blockIdx.x == 0 && threadIdx.x == 0) {
        int flag = 1;
        #pragma unroll
        for (int i = 0; i < 16; i++)
            if (ei32[2 * i + 1] != 0) flag = 0;
        g_idx64 = flag;
    }
    int i = blockIdx.x * blockDim.x + threadIdx.x;
    if (i < N_NODES) g_hist[i] = 0;
    if (i < HID * H3) {
        g_wf2t[i] = __uint_as_float(f2tf32(Wf2[i]));
        g_w1t[i]  = __uint_as_float(f2tf32(W1[i]));
    }
    if (i < H3 * H3) g_w2t[i] = __uint_as_float(f2tf32(W2[i]));
    const int nq4 = N_NODES * HID / 4;
    const int nm4 = N_NODES * H3 / 4;
    float4* o4 = (float4*)out;
    if (i < nq4)            o4[i] = ((const float4*)q)[i];
    else if (i < nq4 + nm4) o4[i] = ((const float4*)mu)[i - nq4];
}

// --------------------------- counting sort by target -----------------------
__global__ void hist_kernel(const int* __restrict__ ei32,
                            const long long* __restrict__ ei64) {
    int e = blockIdx.x * blockDim.x + threadIdx.x;
    if (e < N_EDGES) {
        int t = g_idx64 ? (int)ei64[e] : ei32[e];
        atomicAdd(&g_hist[t], 1);
    }
}

__global__ __launch_bounds__(1024) void scan_kernel() {
    __shared__ int part[1024];
    const int tid = threadIdx.x;
    const int base = tid * 10;
    int local[10];
    int s = 0;
    #pragma unroll
    for (int j = 0; j < 10; j++) {
        int v = (base + j < N_NODES) ? g_hist[base + j] : 0;
        local[j] = s;
        s += v;
    }
    part[tid] = s;
    __syncthreads();
    const int own = s;
    for (int d = 1; d < 1024; d <<= 1) {
        int v = (tid >= d) ? part[tid - d] : 0;
        __syncthreads();
        part[tid] += v;
        __syncthreads();
    }
    int excl = part[tid] - own;
    #pragma unroll
    for (int j = 0; j < 10; j++)
        if (base + j < N_NODES) g_cursor[base + j] = excl + local[j];
}

__global__ void scatter_kernel(const int* __restrict__ ei32,
                               const long long* __restrict__ ei64) {
    int e = blockIdx.x * blockDim.x + threadIdx.x;
    if (e < N_EDGES) {
        int t = g_idx64 ? (int)ei64[e] : ei32[e];
        int pos = atomicAdd(&g_cursor[t], 1);
        g_perm[pos] = e;
    }
}

// ---------------------------------------------------------------------------
// Kernel 2: node MLP via TF32 MMA (unchanged from R10).
// ---------------------------------------------------------------------------
#define SMEM_NODE 115712
#define QPITCH 132
#define TPITCH 388

__global__ __launch_bounds__(256) void node_mma(const float* __restrict__ q,
                                                const float* __restrict__ b1,
                                                const float* __restrict__ b2) {
    extern __shared__ char smem[];
    uint32_t* qs   = (uint32_t*)smem;
    float*    wbuf = (float*)(smem + 16896);
    uint32_t* t1s  = (uint32_t*)(smem + 66048);

    const int tid = threadIdx.x;
    const int n0 = blockIdx.x * NPB;
    const int F4 = KCH * H3 / 4;  // 1536

    auto stage_slot = [&](int slot) {
        float* dst = wbuf + (slot & 1) * KCH * H3;
        const float4* src = (slot < NCHUNK)
            ? (const float4*)g_w1t + slot * F4
            : (const float4*)g_w2t + (slot - NCHUNK) * F4;
        for (int i = tid; i < F4; i += 256) {
            int kk = i / 96;
            int n  = (i % 96) * 4;
            int ns = n ^ ((kk & 3) << 3);
            cp_async16(dst + kk * H3 + ns, src + i);
        }
        cp_commit();
    };

    stage_slot(0);
    stage_slot(1);

    for (int i = tid; i < NPB * (HID / 4); i += 256) {
        int r = i >> 5;
        int c4 = (i & 31) * 4;
        float4 v = (n0 + r < N_NODES)
            ? __ldg((const float4*)(q + (n0 + r) * HID + c4))
            : make_float4(0.f, 0.f, 0.f, 0.f);
        uint32_t* dst = qs + r * QPITCH + c4;
        dst[0] = f2tf32(v.x); dst[1] = f2tf32(v.y);
        dst[2] = f2tf32(v.z); dst[3] = f2tf32(v.w);
    }

    const int warp = tid >> 5, lane = tid & 31;
    const int g = lane >> 2, c = lane & 3;
    const int C0 = warp * 48;

    float d[2][6][4];
    #pragma unroll
    for (int mt = 0; mt < 2; mt++)
        #pragma unroll
        for (int j = 0; j < 6; j++)
            #pragma unroll
            for (int r = 0; r < 4; r++) d[mt][j][r] = 0.f;

    #pragma unroll
    for (int ch = 0; ch < NCHUNK; ch++) {
        cp_wait<1>();
        __syncthreads();
        const float* wch = wbuf + (ch & 1) * KCH * H3;
        #pragma unroll
        for (int ks = 0; ks < 2; ks++) {
            const int kglob = ch * KCH + 8 * ks;
            uint32_t a[2][4];
            #pragma unroll
            for (int mt = 0; mt < 2; mt++) {
                const uint32_t* ap = qs + (16 * mt + g) * QPITCH + kglob + c;
                a[mt][0] = ap[0];
                a[mt][1] = ap[8 * QPITCH];
                a[mt][2] = ap[4];
                a[mt][3] = ap[8 * QPITCH + 4];
            }
            uint32_t b[6][2];
            #pragma unroll
            for (int j = 0; j < 6; j++) {
                const int n = C0 + 8 * j + g;
                const int kk0 = 8 * ks + c;
                b[j][0] = ((const uint32_t*)wch)[kk0 * H3 + (n ^ ((kk0 & 3) << 3))];
                const int kk1 = kk0 + 4;
                b[j][1] = ((const uint32_t*)wch)[kk1 * H3 + (n ^ ((kk1 & 3) << 3))];
            }
            #pragma unroll
            for (int mt = 0; mt < 2; mt++)
                #pragma unroll
                for (int j = 0; j < 6; j++)
                    mma_tf32(d[mt][j], a[mt], b[j]);
        }
        __syncthreads();
        stage_slot(ch + 2);
    }

    #pragma unroll
    for (int mt = 0; mt < 2; mt++)
        #pragma unroll
        for (int j = 0; j < 6; j++) {
            const int C = C0 + 8 * j + 2 * c;
            const float bb0 = __ldg(&b1[C]), bb1 = __ldg(&b1[C + 1]);
            const int r0 = 16 * mt + g;
            float v0 = silu_f(d[mt][j][0] + bb0);
            float v1 = silu_f(d[mt][j][1] + bb1);
            *(ull*)(t1s + r0 * TPITCH + C) =
                pack2(__uint_as_float(f2tf32(v0)), __uint_as_float(f2tf32(v1)));
            float v2 = silu_f(d[mt][j][2] + bb0);
            float v3 = silu_f(d[mt][j][3] + bb1);
            *(ull*)(t1s + (r0 + 8) * TPITCH + C) =
                pack2(__uint_as_float(f2tf32(v2)), __uint_as_float(f2tf32(v3)));
        }
    #pragma unroll
    for (int mt = 0; mt < 2; mt++)
        #pragma unroll
        for (int j = 0; j < 6; j++)
            #pragma unroll
            for (int r = 0; r < 4; r++) d[mt][j][r] = 0.f;

    const int NCH2 = H3 / KCH;   // 24
    for (int ch = 0; ch < NCH2; ch++) {
        if (ch == NCH2 - 1) cp_wait<0>(); else cp_wait<1>();
        __syncthreads();
        const float* wch = wbuf + (ch & 1) * KCH * H3;
        #pragma unroll
        for (int ks = 0; ks < 2; ks++) {
            const int kglob = ch * KCH + 8 * ks;
            uint32_t a[2][4];
            #pragma unroll
            for (int mt = 0; mt < 2; mt++) {
                const uint32_t* ap = t1s + (16 * mt + g) * TPITCH + kglob + c;
                a[mt][0] = ap[0];
                a[mt][1] = ap[8 * TPITCH];
                a[mt][2] = ap[4];
                a[mt][3] = ap[8 * TPITCH + 4];
            }
            uint32_t b[6][2];
            #pragma unroll
            for (int j = 0; j < 6; j++) {
                const int n = C0 + 8 * j + g;
                const int kk0 = 8 * ks + c;
                b[j][0] = ((const uint32_t*)wch)[kk0 * H3 + (n ^ ((kk0 & 3) << 3))];
                const int kk1 = kk0 + 4;
                b[j][1] = ((const uint32_t*)wch)[kk1 * H3 + (n ^ ((kk1 & 3) << 3))];
            }
            #pragma unroll
            for (int mt = 0; mt < 2; mt++)
                #pragma unroll
                for (int j = 0; j < 6; j++)
                    mma_tf32(d[mt][j], a[mt], b[j]);
        }
        __syncthreads();
        if (ch + 2 < NCH2) stage_slot(NCHUNK + ch + 2);
    }

    #pragma unroll
    for (int mt = 0; mt < 2; mt++)
        #pragma unroll
        for (int j = 0; j < 6; j++) {
            const int C = C0 + 8 * j + 2 * c;
            const float bb0 = __ldg(&b2[C]), bb1 = __ldg(&b2[C + 1]);
            const int r0 = n0 + 16 * mt + g;
            if (r0 < N_NODES)
                *(float2*)(g_x + r0 * H3 + C) =
                    make_float2(d[mt][j][0] + bb0, d[mt][j][1] + bb1);
            if (r0 + 8 < N_NODES)
                *(float2*)(g_x + (r0 + 8) * H3 + C) =
                    make_float2(d[mt][j][2] + bb0, d[mt][j][3] + bb1);
        }
}

// ---------------------------------------------------------------------------
// Kernel 3: fused edge kernel — ALL-MMA. 64 sorted edges/block, 512 threads.
// Phase A (rbf@Wf1, K padded 20->24) now runs on tensor cores too.
// Main GEMM: 16 warps, warp = 3 n8-tiles x 4 m16-tiles, K=128 streamed.
// ---------------------------------------------------------------------------
// smem layout:
//   h1s  [64][132] u32  @ 0       (33792)
//   wbuf [2][16][384]   @ 33792   (49152)
//   Wf1s [24][132]      @ 82944   (12672)   rows 20-23 zeroed
//   rbfs [64][36]       @ 95616   (9216)    cols 20-35 zeroed, physical rows
//   bf1s [HID]          @ 104832  (512)
//   bf2s [H3]           @ 105344  (1536)
//   cuts [64]           @ 106880  (256)
//   uvs  [64*3]         @ 107136  (768)
//   srcs [64] int       @ 107904  (256)
//   tgts [64] int       @ 108160  (256)
//   es   [64] int       @ 108416  (256)
#define SMEM_EDGE 108672
#define H1PITCH 132
#define WF1PITCH 132
#define RBFPITCH 36

__global__ __launch_bounds__(EK_THREADS) void edge_kernel(
        const int* __restrict__ ei32, const long long* __restrict__ ei64,
        const float* __restrict__ rbf, const float* __restrict__ uv,
        const float* __restrict__ cut,
        const float* __restrict__ Wf1, const float* __restrict__ bf1,
        const float* __restrict__ bf2,
        const float* __restrict__ mu, float* __restrict__ out) {
    extern __shared__ char smem[];
    uint32_t* h1u  = (uint32_t*)smem;
    float*    wbuf = (float*)(smem + 33792);
    float*    Wf1s = (float*)(smem + 82944);
    float*    rbfs = (float*)(smem + 95616);
    float*    bf1s = (float*)(smem + 104832);
    float*    bf2s = (float*)(smem + 105344);
    float*    cuts = (float*)(smem + 106880);
    float*    uvs  = (float*)(smem + 107136);
    int*      srcs = (int*)(smem + 107904);
    int*      tgts = (int*)(smem + 108160);
    int*      es   = (int*)(smem + 108416);

    const int tid = threadIdx.x;
    const int e0 = blockIdx.x * EPB;
    const int F4 = KCH * H3 / 4;  // 1536

    auto stage_chunk = [&](int chunk, int buf) {
        float* dst = wbuf + buf * KCH * H3;
        const float4* src = (const float4*)g_wf2t + chunk * F4;
        for (int i = tid; i < F4; i += EK_THREADS) {
            int kk = i / 96;
            int n  = (i % 96) * 4;
            int ns = n ^ ((kk & 3) << 3);
            cp_async16(dst + kk * H3 + ns, src + i);
        }
        cp_commit();
    };

    stage_chunk(0, 0);
    stage_chunk(1, 1);

    if (tid < EPB) es[tid] = g_perm[e0 + tid];
    // Wf1 -> smem pitch 132 (tf32 via cvt on load), rows 20-23 zero
    for (int i = tid; i < NRBF * HID; i += EK_THREADS) {
        int k = i >> 7, j = i & 127;
        ((uint32_t*)Wf1s)[k * WF1PITCH + j] = f2tf32(Wf1[i]);
    }
    for (int i = tid; i < 4 * WF1PITCH; i += EK_THREADS)
        Wf1s[NRBF * WF1PITCH + i] = 0.f;
    // zero rbf pad cols 20-35
    for (int i = tid; i < EPB * 4; i += EK_THREADS) {
        int R = i >> 2;
        *(float4*)(rbfs + R * RBFPITCH + 20 + (i & 3) * 4) =
            make_float4(0.f, 0.f, 0.f, 0.f);
    }
    for (int i = tid; i < H3; i += EK_THREADS) bf2s[i] = bf2[i];
    if (tid < HID) bf1s[tid] = bf1[tid];
    __syncthreads();  // es visible

    // per-edge gathers; rbf by PHYSICAL mma row (tf32), rest by sorted order
    {
        const float4* rsrc = (const float4*)rbf;
        for (int i = tid; i < EPB * 5; i += EK_THREADS) {
            int R = i / 5;
            int e = es[sorted_of_row(R)];
            float4 v = __ldg(rsrc + e * 5 + (i % 5));
            uint32_t* dst = (uint32_t*)(rbfs + R * RBFPITCH + (i % 5) * 4);
            dst[0] = f2tf32(v.x); dst[1] = f2tf32(v.y);
            dst[2] = f2tf32(v.z); dst[3] = f2tf32(v.w);
        }
        for (int i = tid; i < EPB * 3; i += EK_THREADS) {
            int e = es[i / 3];
            uvs[i] = uv[e * 3 + (i % 3)];
        }
        if (tid < EPB) {
            int e = es[tid];
            cuts[tid] = cut[e];
            if (g_idx64) { tgts[tid] = (int)ei64[e]; srcs[tid] = (int)ei64[N_EDGES + e]; }
            else         { tgts[tid] = ei32[e];      srcs[tid] = ei32[N_EDGES + e]; }
        }
    }
    __syncthreads();

    const int warp = tid >> 5, lane = tid & 31;
    const int g = lane >> 2, c = lane & 3;

    // Phase A via MMA: h1[64,128] = silu(rbf@Wf1 + bf1), K=24 (3 k-steps).
    // warp -> mt_a = warp>>2 (m16 tile), n8 tiles jbase..jbase+3.
    {
        const int mt_a = warp >> 2;
        const int jbase = (warp & 3) * 4;
        float da[4][4];
        #pragma unroll
        for (int jt = 0; jt < 4; jt++)
            #pragma unroll
            for (int r = 0; r < 4; r++) da[jt][r] = 0.f;

        #pragma unroll
        for (int ks = 0; ks < 3; ks++) {
            uint32_t a[4];
            const uint32_t* ap = (const uint32_t*)rbfs
                                 + (16 * mt_a + g) * RBFPITCH + 8 * ks + c;
            a[0] = ap[0];
            a[1] = ap[8 * RBFPITCH];
            a[2] = ap[4];
            a[3] = ap[8 * RBFPITCH + 4];
            #pragma unroll
            for (int jt = 0; jt < 4; jt++) {
                const int j = jbase + jt;
                uint32_t b[2];
                b[0] = ((const uint32_t*)Wf1s)[(8 * ks + c) * WF1PITCH + 8 * j + g];
                b[1] = ((const uint32_t*)Wf1s)[(8 * ks + c + 4) * WF1PITCH + 8 * j + g];
                mma_tf32(da[jt], a, b);
            }
        }
        // bias + silu -> h1 (tf32), rows 16*mt_a+g and +8
        const int r0 = 16 * mt_a + g;
        #pragma unroll
        for (int jt = 0; jt < 4; jt++) {
            const int col = 8 * (jbase + jt) + 2 * c;
            const float bb0 = bf1s[col], bb1 = bf1s[col + 1];
            float v0 = silu_f(da[jt][0] + bb0);
            float v1 = silu_f(da[jt][1] + bb1);
            *(ull*)(h1u + r0 * H1PITCH + col) =
                pack2(__uint_as_float(f2tf32(v0)), __uint_as_float(f2tf32(v1)));
            float v2 = silu_f(da[jt][2] + bb0);
            float v3 = silu_f(da[jt][3] + bb1);
            *(ull*)(h1u + (r0 + 8) * H1PITCH + col) =
                pack2(__uint_as_float(f2tf32(v2)), __uint_as_float(f2tf32(v3)));
        }
    }

    // Phase B: main TF32 MMA. warp owns cols [warp*24, warp*24+24) = 3 n8,
    // all 4 m16 tiles (64 edges).
    const int C0 = warp * 24;

    float d[4][3][4];
    #pragma unroll
    for (int mt = 0; mt < 4; mt++)
        #pragma unroll
        for (int j = 0; j < 3; j++)
            #pragma unroll
            for (int r = 0; r < 4; r++) d[mt][j][r] = 0.f;

    #pragma unroll
    for (int chunk = 0; chunk < NCHUNK; chunk++) {
        if (chunk == NCHUNK - 1) cp_wait<0>(); else cp_wait<1>();
        __syncthreads();   // chunk ready; for chunk 0 also orders h1 writes
        const float* wch = wbuf + (chunk & 1) * KCH * H3;
        #pragma unroll
        for (int ks = 0; ks < 2; ks++) {
            const int kglob = chunk * KCH + 8 * ks;
            uint32_t a[4][4];
            #pragma unroll
            for (int mt = 0; mt < 4; mt++) {
                const uint32_t* hp = h1u + (16 * mt + g) * H1PITCH + kglob + c;
                a[mt][0] = hp[0];
                a[mt][1] = hp[8 * H1PITCH];
                a[mt][2] = hp[4];
                a[mt][3] = hp[8 * H1PITCH + 4];
            }
            uint32_t b[3][2];
            #pragma unroll
            for (int j = 0; j < 3; j++) {
                const int n = C0 + 8 * j + g;
                const int kk0 = 8 * ks + c;
                b[j][0] = ((const uint32_t*)wch)[kk0 * H3 + (n ^ ((kk0 & 3) << 3))];
                const int kk1 = kk0 + 4;
                b[j][1] = ((const uint32_t*)wch)[kk1 * H3 + (n ^ ((kk1 & 3) << 3))];
            }
            #pragma unroll
            for (int mt = 0; mt < 4; mt++)
                #pragma unroll
                for (int j = 0; j < 3; j++)
                    mma_tf32(d[mt][j], a[mt], b[j]);
        }
        __syncthreads();
        if (chunk + 2 < NCHUNK) stage_chunk(chunk + 2, chunk & 1);
    }

    // Phase C: epilogue, j-outer, run-combined scatter.
    // Lane owns sorted edges s = 8g+idx, idx 0..7; R = 16*(idx>>1)+8*(idx&1)+g.
    float* outq  = out;
    float* outmu = out + N_NODES * HID;

    #pragma unroll
    for (int j = 0; j < 3; j++) {
        const int C = C0 + 8 * j + 2 * c;
        const int part = C >> 7, jj = C & 127;
        const float b0 = bf2s[C], b1v = bf2s[C + 1];
        float a0 = 0.f, a1 = 0.f;
        float v[3][2] = {{0.f,0.f},{0.f,0.f},{0.f,0.f}};

        #pragma unroll
        for (int idx = 0; idx < 8; idx++) {
            const int s = 8 * g + idx;
            const int mt = idx >> 1, h = idx & 1;
            const float cs = cuts[s];
            const int src = srcs[s], tgt = tgts[s];
            const float* xb = g_x + src * H3;
            float f0 = (d[mt][j][2 * h]     + b0)  * cs;
            float f1 = (d[mt][j][2 * h + 1] + b1v) * cs;

            if (part == 0) {
                float2 x2 = __ldg((const float2*)(xb + jj));
                a0 += x2.x * f0;
                a1 += x2.y * f1;
            } else if (part == 1) {
                float2 x2 = __ldg((const float2*)(xb + HID + jj));
                float t0 = x2.x * f0, t1 = x2.y * f1;
                #pragma unroll
                for (int dd = 0; dd < 3; dd++) {
                    float u = uvs[s * 3 + dd];
                    v[dd][0] += u * t0;
                    v[dd][1] += u * t1;
                }
            } else {
                float2 x2 = __ldg((const float2*)(xb + 2 * HID + jj));
                float t0 = x2.x * f0, t1 = x2.y * f1;
                #pragma unroll
                for (int dd = 0; dd < 3; dd++) {
                    float2 m2 = __ldg((const float2*)(mu + (src * 3 + dd) * HID + jj));
                    v[dd][0] += m2.x * t0;
                    v[dd][1] += m2.y * t1;
                }
            }

            const bool flush = (idx == 7) || (tgts[s + 1] != tgt);
            if (flush) {
                if (part == 0) {
                    red_add_v2(outq + tgt * HID + jj, a0, a1);
                    a0 = 0.f; a1 = 0.f;
                } else {
                    #pragma unroll
                    for (int dd = 0; dd < 3; dd++) {
                        red_add_v2(outmu + (tgt * 3 + dd) * HID + jj, v[dd][0], v[dd][1]);
                        v[dd][0] = 0.f; v[dd][1] = 0.f;
                    }
                }
            }
        }
    }
}

extern "C" void kernel_launch(void* const* d_in, const int* in_sizes, int n_in,
                              void* d_out, int out_size) {
    const float* q   = (const float*)d_in[0];
    const float* mu  = (const float*)d_in[1];
    const void*  ei  = d_in[2];
    const float* rbf = (const float*)d_in[3];
    const float* uvp = (const float*)d_in[4];
    const float* cut = (const float*)d_in[5];
    const float* W1  = (const float*)d_in[6];
    const float* b1  = (const float*)d_in[7];
    const float* W2  = (const float*)d_in[8];
    const float* b2  = (const float*)d_in[9];
    const float* Wf1 = (const float*)d_in[10];
    const float* bf1 = (const float*)d_in[11];
    const float* Wf2 = (const float*)d_in[12];
    const float* bf2 = (const float*)d_in[13];
    float* out = (float*)d_out;

    cudaFuncSetAttribute(edge_kernel,
                         cudaFuncAttributeMaxDynamicSharedMemorySize, SMEM_EDGE);
    cudaFuncSetAttribute(node_mma,
                         cudaFuncAttributeMaxDynamicSharedMemorySize, SMEM_NODE);

    const int total4 = N_NODES * (HID + H3) / 4;
    init_out<<<(total4 + 255) / 256, 256>>>(q, mu, out, (const int*)ei, Wf2, W1, W2);
    hist_kernel<<<(N_EDGES + 255) / 256, 256>>>((const int*)ei, (const long long*)ei);
    scan_kernel<<<1, 1024>>>();
    scatter_kernel<<<(N_EDGES + 255) / 256, 256>>>((const int*)ei, (const long long*)ei);
    node_mma<<<(N_NODES + NPB - 1) / NPB, 256, SMEM_NODE>>>(q, b1, b2);
    edge_kernel<<<N_EDGES / EPB, EK_THREADS, SMEM_EDGE>>>(
        (const int*)ei, (const long long*)ei,
        rbf, uvp, cut, Wf1, bf1, bf2, mu, out);
}